// round 8
// baseline (speedup 1.0000x reference)
#include <cuda_runtime.h>
#include <cuda_fp16.h>
#include <math.h>
#include <stdint.h>

#define NB 16
#define ROWS 16384

// ---------------- device scratch ----------------
__device__ __align__(16) __half g_Hh[(size_t)NB * 128 * ROWS];  // [b][z][row] fp16
__device__ float g_P[NB * 1024];
__device__ float g_part[NB * 16 * 256];
__device__ __align__(16) __half g_W1f[11 * 8192];   // pre-swizzled k32 chunks
__device__ __align__(16) __half g_W2f[8 * 4096];    // pre-swizzled k32 chunks

// ---------------- smem layout (bytes) ----------------
#define C1H 0                          // 64 x 264 halves (pitch 528B) = 33792
#define A1F(bi) (33792 + (bi) * 4096)  // A tile 64 x 32k, pitch 64B, XOR swizzle
#define B1F(bi) (41984 + (bi) * 16384) // B tile 256 x 32k, pitch 64B, XOR swizzle
#define B2F(bi) (33792 + (bi) * 8192)  // stage2 B 128 x 32k (reuses stage1 region)
#define STG 0                          // epi-2 staging reuses C1: 128 x 144B
#define SMEM_TOTAL 74752

// ---------------- helpers ----------------
__device__ __forceinline__ uint32_t smem_u32(const void* p) {
    uint32_t a;
    asm("{ .reg .u64 t; cvta.to.shared.u64 t, %1; cvt.u32.u64 %0, t; }" : "=r"(a) : "l"(p));
    return a;
}
__device__ __forceinline__ void ldmat4(uint32_t addr, uint32_t r[4]) {
    asm volatile("ldmatrix.sync.aligned.m8n8.x4.shared.b16 {%0,%1,%2,%3}, [%4];"
        : "=r"(r[0]), "=r"(r[1]), "=r"(r[2]), "=r"(r[3]) : "r"(addr) : "memory");
}
__device__ __forceinline__ void mma16816(float d[4], const uint32_t a[4],
                                         uint32_t b0, uint32_t b1) {
    asm volatile("mma.sync.aligned.m16n8k16.row.col.f32.f16.f16.f32 "
        "{%0,%1,%2,%3}, {%4,%5,%6,%7}, {%8,%9}, {%0,%1,%2,%3};"
        : "+f"(d[0]), "+f"(d[1]), "+f"(d[2]), "+f"(d[3])
        : "r"(a[0]), "r"(a[1]), "r"(a[2]), "r"(a[3]), "r"(b0), "r"(b1));
}
__device__ __forceinline__ uint32_t packh2(float x, float y) {
    __half2 h = __floats2half2_rn(x, y);
    return *(uint32_t*)&h;
}
__device__ __forceinline__ const float* selsrc(int s, const float* a, const float* b,
                                               const float* c, const float* d) {
    return s == 0 ? a : (s == 1 ? b : (s == 2 ? c : d));
}

// ============================================================
// prep: W1/W2 -> fp16, k32-chunked, XOR-swizzled (phys chunk = h ^ ((n>>1)&3))
// ============================================================
__global__ void prep_w_kernel(const float* __restrict__ W1, const float* __restrict__ W2)
{
    int idx = blockIdx.x * 256 + threadIdx.x;     // 480*256 = 122880
    if (idx < 90112) {                             // W1: 11 chunks x 256n x 32k
        int n = idx & 255;
        int q = idx >> 8;                          // 0..351
        int c = q >> 5;
        int t = q & 31, h = t >> 3, j = t & 7;
        int k = c * 32 + h * 8 + j;
        float w = (k < 324) ? W1[k * 256 + n] : 0.f;
        int u = n * 4 + (h ^ ((n >> 1) & 3));
        g_W1f[c * 8192 + u * 8 + j] = __float2half_rn(w);
    } else {                                       // W2: 8 chunks x 128n x 32k
        int m = idx - 90112;
        int n = m & 127;
        int q = m >> 7;                            // 0..255
        int c = q >> 5;
        int t = q & 31, h = t >> 3, j = t & 7;
        int k = c * 32 + h * 8 + j;
        float w = W2[k * 128 + n];
        int u = n * 4 + (h ^ ((n >> 1) & 3));
        g_W2f[c * 4096 + u * 8 + j] = __float2half_rn(w);
    }
}

// ============================================================
// fused GEMM1 -> ReLU -> GEMM2, fp16 MMA, k32 chunks, XOR-swizzled smem
// CTA: 256 threads (2M x 4N warps), 64 rows, 2 CTAs/SM. grid (256, 16).
// ============================================================
__global__ void __launch_bounds__(256, 2) gemm_mma_kernel(
    const float* __restrict__ fgc, const float* __restrict__ fgt,
    const float* __restrict__ bgc, const float* __restrict__ bgt,
    const float* __restrict__ b1, const float* __restrict__ b2)
{
    extern __shared__ char sm[];
    const uint32_t smb = smem_u32(sm);
    const int tid = threadIdx.x, lane = tid & 31, warp = tid >> 5;
    const int wm = warp & 1, wn = warp >> 1;          // 2 x 4
    const int b = blockIdx.y;
    const int row0 = blockIdx.x * 64;
    const int g = lane >> 2, tg = lane & 3;

    // gather mapping: thread -> (row gr, k-octet gkq)
    const int gr = tid >> 2;                          // 0..63
    const int gkq = tid & 3;                          // 0..3
    const int R = row0 + gr;
    const uint32_t gsts_off = (uint32_t)(gr * 64 + ((gkq ^ ((gr >> 1) & 3)) << 4));

    // MMA addressing (invariant under +16 row shift)
    const int arow = wm * 32 + (lane & 15);
    const int hsel = lane >> 4;
    const uint32_t aswz = (arow >> 1) & 3;
    const int nrow1 = wn * 64 + (lane & 15);
    const uint32_t bswz1 = (nrow1 >> 1) & 3;

    float acc[2][8][4];
    #pragma unroll
    for (int i = 0; i < 2; ++i)
        #pragma unroll
        for (int j = 0; j < 8; ++j)
            #pragma unroll
            for (int r = 0; r < 4; ++r) acc[i][j][r] = 0.f;

    float f[8];
    uint4 wv[4];

    // gather chunk c into f
    auto gatherK = [&](int c, float* fo) {
        #pragma unroll
        for (int j = 0; j < 8; ++j) {
            int k = c * 32 + gkq * 8 + j;
            float v = 0.f;
            if (k < 324) {
                int t = k / 12, rem = k - t * 12, s = rem / 3, cm = rem - s * 3;
                const float* sp = selsrc(s, fgc, fgt, bgc, bgt);
                v = sp[((size_t)(b * 27 + t) * ROWS + R) * 3 + cm];
            }
            fo[j] = v;
        }
    };

    // ---- prologue ----
    gatherK(0, f);
    {
        uint32_t u0 = packh2(f[0], f[1]), u1 = packh2(f[2], f[3]);
        uint32_t u2 = packh2(f[4], f[5]), u3 = packh2(f[6], f[7]);
        asm volatile("st.shared.v4.b32 [%0], {%1,%2,%3,%4};"
            :: "r"(smb + A1F(0) + gsts_off), "r"(u0), "r"(u1), "r"(u2), "r"(u3) : "memory");
    }
    {
        const uint4* s = (const uint4*)(g_W1f);
        #pragma unroll
        for (int i = 0; i < 4; ++i)
            *(uint4*)(sm + B1F(0) + (tid + i * 256) * 16) = s[tid + i * 256];
    }
    gatherK(1, f);
    __syncthreads();

    // ---- stage 1: 11 chunks of k32 ----
    for (int c = 0; c < 11; ++c) {
        const int bi = c & 1;
        if (c < 10) {
            uint32_t u0 = packh2(f[0], f[1]), u1 = packh2(f[2], f[3]);
            uint32_t u2 = packh2(f[4], f[5]), u3 = packh2(f[6], f[7]);
            asm volatile("st.shared.v4.b32 [%0], {%1,%2,%3,%4};"
                :: "r"(smb + A1F(bi ^ 1) + gsts_off), "r"(u0), "r"(u1), "r"(u2), "r"(u3) : "memory");
            const uint4* s = (const uint4*)(g_W1f + (c + 1) * 8192);
            #pragma unroll
            for (int i = 0; i < 4; ++i) wv[i] = s[tid + i * 256];
        }
        float f2[8];
        if (c < 9) gatherK(c + 2, f2);

        // MMA chunk c
        const uint32_t abase = smb + A1F(bi) + arow * 64;
        const uint32_t bbase = smb + B1F(bi);
        #pragma unroll
        for (int kc = 0; kc < 2; ++kc) {
            uint32_t ah[2][4];
            uint32_t ac = (uint32_t)(((2 * kc + hsel) ^ aswz) << 4);
            ldmat4(abase + ac, ah[0]);
            ldmat4(abase + 16 * 64 + ac, ah[1]);
            uint32_t bc = (uint32_t)(((2 * kc + hsel) ^ bswz1) << 4);
            #pragma unroll
            for (int jj = 0; jj < 4; ++jj) {
                uint32_t bh[4];
                ldmat4(bbase + (nrow1 + jj * 16) * 64 + bc, bh);
                #pragma unroll
                for (int i = 0; i < 2; ++i)
                    #pragma unroll
                    for (int jn = 0; jn < 2; ++jn)
                        mma16816(acc[i][jj * 2 + jn], ah[i], bh[jn], bh[jn + 2]);
            }
        }

        if (c < 10) {
            #pragma unroll
            for (int i = 0; i < 4; ++i)
                *(uint4*)(sm + B1F(bi ^ 1) + (tid + i * 256) * 16) = wv[i];
        }
        if (c < 9) {
            #pragma unroll
            for (int j = 0; j < 8; ++j) f[j] = f2[j];
        }
        __syncthreads();
    }

    // ---- epilogue 1: bias + relu + fp16 -> C1 smem (pitch 528B) ----
    #pragma unroll
    for (int i = 0; i < 2; ++i) {
        int m0 = wm * 32 + i * 16 + g;
        #pragma unroll
        for (int j = 0; j < 8; ++j) {
            int n = wn * 64 + j * 8 + tg * 2;
            float bn0 = b1[n], bn1 = b1[n + 1];
            float x0 = fmaxf(acc[i][j][0] + bn0, 0.f);
            float x1 = fmaxf(acc[i][j][1] + bn1, 0.f);
            float x2 = fmaxf(acc[i][j][2] + bn0, 0.f);
            float x3 = fmaxf(acc[i][j][3] + bn1, 0.f);
            *(uint32_t*)(sm + C1H + m0 * 528 + n * 2)       = packh2(x0, x1);
            *(uint32_t*)(sm + C1H + (m0 + 8) * 528 + n * 2) = packh2(x2, x3);
        }
    }
    __syncthreads();

    // ---- stage 2: C2 = C1 @ W2, 8 chunks of k32 ----
    float acc2[2][4][4];
    #pragma unroll
    for (int i = 0; i < 2; ++i)
        #pragma unroll
        for (int j = 0; j < 4; ++j)
            #pragma unroll
            for (int r = 0; r < 4; ++r) acc2[i][j][r] = 0.f;

    {
        const uint4* s = (const uint4*)(g_W2f);
        *(uint4*)(sm + B2F(0) + tid * 16)         = s[tid];
        *(uint4*)(sm + B2F(0) + (tid + 256) * 16) = s[tid + 256];
    }
    __syncthreads();

    const int nrow2 = wn * 32 + (lane & 15);
    const uint32_t bswz2 = (nrow2 >> 1) & 3;

    for (int c = 0; c < 8; ++c) {
        const int bi = c & 1;
        uint4 w0, w1;
        if (c < 7) {
            const uint4* s = (const uint4*)(g_W2f + (c + 1) * 4096);
            w0 = s[tid]; w1 = s[tid + 256];
        }
        const uint32_t abase = smb + C1H + arow * 528 + c * 64;
        const uint32_t bbase = smb + B2F(bi);
        #pragma unroll
        for (int kc = 0; kc < 2; ++kc) {
            uint32_t ah[2][4];
            uint32_t ac = (uint32_t)((2 * kc + hsel) * 16);
            ldmat4(abase + ac, ah[0]);
            ldmat4(abase + 16 * 528 + ac, ah[1]);
            uint32_t bc = (uint32_t)(((2 * kc + hsel) ^ bswz2) << 4);
            #pragma unroll
            for (int jg = 0; jg < 2; ++jg) {
                uint32_t bh[4];
                ldmat4(bbase + (nrow2 + jg * 16) * 64 + bc, bh);
                #pragma unroll
                for (int i = 0; i < 2; ++i)
                    #pragma unroll
                    for (int jn = 0; jn < 2; ++jn)
                        mma16816(acc2[i][jg * 2 + jn], ah[i], bh[jn], bh[jn + 2]);
            }
        }
        if (c < 7) {
            *(uint4*)(sm + B2F(bi ^ 1) + tid * 16)         = w0;
            *(uint4*)(sm + B2F(bi ^ 1) + (tid + 256) * 16) = w1;
        }
        __syncthreads();
    }

    // ---- epilogue 2: + b2 -> fp16 staging smem [z][m] (pitch 144B) ----
    #pragma unroll
    for (int i = 0; i < 2; ++i) {
        int m0 = wm * 32 + i * 16 + g;
        #pragma unroll
        for (int j = 0; j < 4; ++j) {
            int z = wn * 32 + j * 8 + tg * 2;
            float bz0 = b2[z], bz1 = b2[z + 1];
            *(__half*)(sm + STG + z * 144 + m0 * 2)             = __float2half_rn(acc2[i][j][0] + bz0);
            *(__half*)(sm + STG + (z + 1) * 144 + m0 * 2)       = __float2half_rn(acc2[i][j][1] + bz1);
            *(__half*)(sm + STG + z * 144 + (m0 + 8) * 2)       = __float2half_rn(acc2[i][j][2] + bz0);
            *(__half*)(sm + STG + (z + 1) * 144 + (m0 + 8) * 2) = __float2half_rn(acc2[i][j][3] + bz1);
        }
    }
    __syncthreads();

    #pragma unroll
    for (int e = tid; e < 1024; e += 256) {
        int z = e >> 3, q = e & 7;
        uint4 v = *(uint4*)(sm + STG + z * 144 + q * 16);
        *(uint4*)(g_Hh + ((size_t)b * 128 + z) * ROWS + row0 + q * 8) = v;
    }
}

// ============================================================
// invariant pooling + vector_log (CTA per (b,z)), fp16 input
// ============================================================
__global__ void pool_kernel()
{
    extern __shared__ float S[];
    const int tid = threadIdx.x;
    const int bz = blockIdx.x;
    const __half2* src = (const __half2*)(g_Hh + (size_t)bz * ROWS);
    for (int e = tid; e < 8192; e += 128) {
        float2 v = __half22float2(src[e]);
        int row = e >> 6, col = (e & 63) * 2;
        S[row * 129 + col] = v.x;
        S[row * 129 + col + 1] = v.y;
    }
    __syncthreads();
    const int a = tid;
    const float* rowp = S + a * 129;
    float d = rowp[a], r = 0.f, c = 0.f, p4 = 0.f, p5 = 0.f;
    #pragma unroll 4
    for (int bb = 0; bb < 128; ++bb) {
        float xab = rowp[bb], xba = S[bb * 129 + a];
        r += xab; c += xba;
        p4 = fmaf(xab, xab, p4);
        p5 = fmaf(xab, xba, p5);
    }
    float vals[8] = { d, r, d * d, d * r, p4, p5, r * r, r * c };
    __syncthreads();
    float* red = S;
    #pragma unroll
    for (int q = 0; q < 8; ++q) {
        float v = vals[q];
        #pragma unroll
        for (int off = 16; off > 0; off >>= 1)
            v += __shfl_down_sync(0xffffffff, v, off);
        if ((tid & 31) == 0) red[(tid >> 5) * 8 + q] = v;
    }
    __syncthreads();
    if (tid < 8) {
        float h = red[tid] + red[8 + tid] + red[16 + tid] + red[24 + tid];
        const float denom[8] = {128.f, 16384.f, 128.f, 16384.f,
                                16384.f, 16384.f, 2097152.f, 2097152.f};
        float p = h / denom[tid];
        float vl = copysignf(log1pf(fabsf(p)) * 0.1f, p);
        g_P[(bz >> 7) * 1024 + tid * 128 + (bz & 127)] = vl;
    }
}

// ============================================================
// mlp2a: split-K partials (grid 16 x 16)
// ============================================================
__global__ void mlp2a_kernel(const float* __restrict__ W3)
{
    const int r = blockIdx.x, h = blockIdx.y;
    const int n = threadIdx.x;               // 256
    const float* p = g_P + r * 1024 + h * 64;
    const float* w = W3 + (size_t)h * 64 * 256;
    float acc = 0.f;
    #pragma unroll 8
    for (int k = 0; k < 64; ++k)
        acc = fmaf(p[k], w[k * 256 + n], acc);
    g_part[(r * 16 + h) * 256 + n] = acc;
}

// ============================================================
// mlp2b: reduce partials + bias/relu + final GEMV + tanh
// ============================================================
__global__ void mlp2b_kernel(const float* __restrict__ b3,
                             const float* __restrict__ W4, const float* __restrict__ b4,
                             float* __restrict__ out)
{
    __shared__ float H2[16 * 256];
    const int tid = threadIdx.x;              // 512
    for (int e = tid; e < 4096; e += 512) {
        int r = e >> 8, n = e & 255;
        float s = 0.f;
        #pragma unroll
        for (int h = 0; h < 16; ++h) s += g_part[(r * 16 + h) * 256 + n];
        H2[e] = fmaxf(s + b3[n], 0.f);
    }
    __syncthreads();
    const int o = tid >> 4, g = tid & 15;     // 32 outputs x 16-way
    const int r = o >> 1, c = o & 1;
    float s = 0.f;
    #pragma unroll 4
    for (int k = g; k < 256; k += 16)
        s = fmaf(H2[r * 256 + k], W4[k * 2 + c], s);
    s += __shfl_down_sync(0xffffffff, s, 8, 16);
    s += __shfl_down_sync(0xffffffff, s, 4, 16);
    s += __shfl_down_sync(0xffffffff, s, 2, 16);
    s += __shfl_down_sync(0xffffffff, s, 1, 16);
    if (g == 0) out[o] = tanhf(s + b4[c]) * 8.0f;
}

// ============================================================
extern "C" void kernel_launch(void* const* d_in, const int* in_sizes, int n_in,
                              void* d_out, int out_size)
{
    const float* fgc = (const float*)d_in[0];
    const float* fgt = (const float*)d_in[1];
    const float* bgc = (const float*)d_in[2];
    const float* bgt = (const float*)d_in[3];
    const float* W1  = (const float*)d_in[4];
    const float* b1  = (const float*)d_in[5];
    const float* W2  = (const float*)d_in[6];
    const float* b2  = (const float*)d_in[7];
    const float* W3  = (const float*)d_in[8];
    const float* b3  = (const float*)d_in[9];
    const float* W4  = (const float*)d_in[10];
    const float* b4  = (const float*)d_in[11];
    float* out = (float*)d_out;

    cudaFuncSetAttribute(gemm_mma_kernel, cudaFuncAttributeMaxDynamicSharedMemorySize, SMEM_TOTAL);
    cudaFuncSetAttribute(pool_kernel,     cudaFuncAttributeMaxDynamicSharedMemorySize, 128 * 129 * 4);

    prep_w_kernel<<<480, 256>>>(W1, W2);
    gemm_mma_kernel<<<dim3(256, NB), 256, SMEM_TOTAL>>>(fgc, fgt, bgc, bgt, b1, b2);
    pool_kernel<<<NB * 128, 128, 128 * 129 * 4>>>();
    mlp2a_kernel<<<dim3(16, 16), 256>>>(W3);
    mlp2b_kernel<<<1, 512>>>(b3, W4, b4, out);
}